// round 7
// baseline (speedup 1.0000x reference)
#include <cuda_runtime.h>

#define NODES 2048
#define EDGES 65536
#define D     128
#define NB    16          // nodes per precompute block
#define CAP   128         // bucket capacity per target (in-degree ~Poisson(32))
#define EPSF  1e-6f

// ---------------- scratch (no allocation; zero-initialized at module load) ----------------
__device__ int   g_cursor[NODES];             // per-target count (reset by k_agg each replay)
__device__ int   g_bucket[NODES * CAP];       // src ids grouped by target
__device__ __align__(16) float g_P[NODES * D];   // x @ fW[:128,:]
__device__ __align__(16) float g_Q[NODES * D];   // x @ fW[128:,:]
__device__ float g_es[NODES];                 // exp(s[n]),  s = x@wW[:128]
__device__ float g_et[NODES];                 // exp(t[n]),  t = x@wW[128:]

// ---------------- kernel 1: split P/Q GEMM (half of fW in smem) + es,et + scatter ----------
// Blocks 0..127 compute P (fW[:128]); blocks 128..255 compute Q (fW[128:]).
// 64KB dynamic smem per block -> 2 resident blocks/SM.
extern __shared__ float s_w[];   // [D*D] = one half of fW

__global__ __launch_bounds__(256) void k_pre(const float* __restrict__ x,
                                             const float* __restrict__ fW,
                                             const float* __restrict__ wW,
                                             const int* __restrict__ src,
                                             const int* __restrict__ tgt) {
    __shared__ float xs[D][NB + 2];   // k-major x tile, padded (8B-aligned rows)
    __shared__ float wWs[2 * D];
    __shared__ float red[128];
    int tid = threadIdx.x;
    int isQ = (blockIdx.x >= 128);
    int blk = blockIdx.x & 127;
    int nb  = blk * NB;

    // direct scatter: 256 edges per block (1/thread), hidden behind the staging
    {
        int e = blockIdx.x * 256 + tid;
        int t = tgt[e];
        int pos = atomicAdd(&g_cursor[t], 1);
        if (pos < CAP) g_bucket[t * CAP + pos] = src[e];
    }

    // stage this variant's half of fW (64KB, 16 float4/thread), x tile, wW
    {
        const float4* s4 = reinterpret_cast<const float4*>(fW + (isQ ? D * D : 0));
        float4*       d4 = reinterpret_cast<float4*>(s_w);
#pragma unroll
        for (int r = 0; r < (D * D / 4) / 256; r++)
            d4[tid + r * 256] = s4[tid + r * 256];
    }
    for (int i = tid; i < NB * D; i += 256) {
        int n = i >> 7, k = i & 127;
        xs[k][n] = x[(nb + n) * D + k];
    }
    wWs[tid] = wW[tid];
    __syncthreads();

    // each thread: output column j, 8 nodes, 4 packed f32x2 accumulators
    int j = tid & 127, g = tid >> 7;
    int xbase = g * 8;
    const float* sw = s_w + j;
    unsigned long long a0 = 0, a1 = 0, a2 = 0, a3 = 0;

#pragma unroll 8
    for (int k = 0; k < D; k++) {
        float w = sw[k * D];
        unsigned long long ww;
        asm("mov.b64 %0,{%1,%1};" : "=l"(ww) : "f"(w));
        const unsigned long long* xr =
            reinterpret_cast<const unsigned long long*>(&xs[k][xbase]);
        unsigned long long x0 = xr[0], x1 = xr[1], x2 = xr[2], x3 = xr[3];
        asm("fma.rn.f32x2 %0,%1,%2,%0;" : "+l"(a0) : "l"(x0), "l"(ww));
        asm("fma.rn.f32x2 %0,%1,%2,%0;" : "+l"(a1) : "l"(x1), "l"(ww));
        asm("fma.rn.f32x2 %0,%1,%2,%0;" : "+l"(a2) : "l"(x2), "l"(ww));
        asm("fma.rn.f32x2 %0,%1,%2,%0;" : "+l"(a3) : "l"(x3), "l"(ww));
    }

    float* dst = isQ ? g_Q : g_P;
    float lo, hi;
#define STORE_PAIR(acc, i) \
    asm("mov.b64 {%0,%1},%2;" : "=f"(lo), "=f"(hi) : "l"(acc)); \
    dst[(nb + xbase + 2*(i)    ) * D + j] = lo; \
    dst[(nb + xbase + 2*(i) + 1) * D + j] = hi;
    STORE_PAIR(a0, 0) STORE_PAIR(a1, 1) STORE_PAIR(a2, 2) STORE_PAIR(a3, 3)
#undef STORE_PAIR

    // s,t + exp: only in P-variant blocks (one writer per node)
    if (!isQ) {
        if (tid < 128) {
            int n = tid & 15, half = (tid >> 4) & 1, q = tid >> 5;
            const float* wv = wWs + half * D;
            float p = 0.f;
#pragma unroll 8
            for (int k = q * 32; k < q * 32 + 32; k++) p = fmaf(xs[k][n], wv[k], p);
            red[tid] = p;
        }
        __syncthreads();
        if (tid < 32) {
            float v = red[tid] + red[tid + 32] + red[tid + 64] + red[tid + 96];
            float ev = __expf(v);
            int n = tid & 15, half = tid >> 4;
            if (half) g_et[nb + n] = ev; else g_es[nb + n] = ev;
        }
    }
}

// ---------------- kernel 2: warp-per-node aggregation (no smem, no syncthreads) ------------
__global__ __launch_bounds__(256) void k_agg(float* __restrict__ out,
                                             const float* __restrict__ fb) {
    int lane = threadIdx.x & 31, warp = threadIdx.x >> 5;
    int n = blockIdx.x * 8 + warp;

    int cnt = min(g_cursor[n], CAP);
    if (lane == 0) g_cursor[n] = 0;   // reset for next replay (value already read)
    const int* bk = &g_bucket[n * CAP];

    float4 q4 = *reinterpret_cast<const float4*>(&g_Q[n * D + lane * 4]);
    float4 f4 = *reinterpret_cast<const float4*>(&fb[lane * 4]);
    float4 qf = make_float4(q4.x + f4.x, q4.y + f4.y, q4.z + f4.z, q4.w + f4.w);

    float4 acc = make_float4(0.f, 0.f, 0.f, 0.f);
    float asum = 0.f;

    int i = 0;
    for (; i + 8 <= cnt; i += 8) {
        int   sid[8];
        float w[8];
#pragma unroll
        for (int u = 0; u < 8; u++) sid[u] = __ldg(bk + i + u);       // MLP 8, independent
#pragma unroll
        for (int u = 0; u < 8; u++) w[u] = g_es[sid[u]];              // MLP 8, 1 dep hop
#pragma unroll
        for (int u = 0; u < 8; u++) {
            float4 p = *reinterpret_cast<const float4*>(&g_P[sid[u] * D + lane * 4]);
            acc.x = fmaf(fmaxf(p.x + qf.x, 0.f), w[u], acc.x);
            acc.y = fmaf(fmaxf(p.y + qf.y, 0.f), w[u], acc.y);
            acc.z = fmaf(fmaxf(p.z + qf.z, 0.f), w[u], acc.z);
            acc.w = fmaf(fmaxf(p.w + qf.w, 0.f), w[u], acc.w);
            asum += w[u];
        }
    }
    for (; i < cnt; i++) {
        int   sid = __ldg(bk + i);
        float w   = g_es[sid];
        float4 p  = *reinterpret_cast<const float4*>(&g_P[sid * D + lane * 4]);
        acc.x = fmaf(fmaxf(p.x + qf.x, 0.f), w, acc.x);
        acc.y = fmaf(fmaxf(p.y + qf.y, 0.f), w, acc.y);
        acc.z = fmaf(fmaxf(p.z + qf.z, 0.f), w, acc.z);
        acc.w = fmaf(fmaxf(p.w + qf.w, 0.f), w, acc.w);
        asum += w;
    }

    // asum is lane-uniform; acc holds this lane's 4 features -> direct store
    float et = g_et[n];
    float inv = 1.f / (et * asum + EPSF);
    float4 o = make_float4(et * acc.x * inv, et * acc.y * inv,
                           et * acc.z * inv, et * acc.w * inv);
    *reinterpret_cast<float4*>(&out[n * D + lane * 4]) = o;
}

// ---------------- launch: two graph nodes ----------------
extern "C" void kernel_launch(void* const* d_in, const int* in_sizes, int n_in,
                              void* d_out, int out_size) {
    const float* x   = (const float*)d_in[0];
    const int*   src = (const int*)  d_in[2];
    const int*   tgt = (const int*)  d_in[3];
    const float* fW  = (const float*)d_in[6];
    const float* fb  = (const float*)d_in[7];
    const float* wW  = (const float*)d_in[8];
    float*       out = (float*)d_out;

    static bool attr_done = false;
    if (!attr_done) {
        cudaFuncSetAttribute(k_pre, cudaFuncAttributeMaxDynamicSharedMemorySize,
                             D * D * (int)sizeof(float));
        attr_done = true;
    }

    k_pre<<<256, 256, D * D * sizeof(float)>>>(x, fW, wW, src, tgt);
    k_agg<<<NODES / 8, 256>>>(out, fb);
}

// round 8
// speedup vs baseline: 1.2684x; 1.2684x over previous
#include <cuda_runtime.h>

#define NODES 2048
#define EDGES 65536
#define D     128
#define NB    16          // nodes per precompute tile
#define CAP   128         // bucket capacity per target (in-degree ~Poisson(32))
#define EPSF  1e-6f

// ---------------- scratch (no allocation; zero-initialized at module load) ----------------
__device__ int   g_cursor[NODES];             // per-target count (reset by k_agg each replay)
__device__ int   g_bucket[NODES * CAP];       // src ids grouped by target
__device__ __align__(16) float g_P[NODES * D];   // x @ fW[:128,:]
__device__ __align__(16) float g_Q[NODES * D];   // x @ fW[128:,:]
__device__ float g_es[NODES];                 // exp(s[n]),  s = x@wW[:128]
__device__ float g_et[NODES];                 // exp(t[n]),  t = x@wW[128:]

// ---------------- kernel 1: quarter-tile GEMM + es,et + direct bucket scatter --------------
// 512 blocks: blk = node tile (0..127), isQ = P/Q half, jh = 64-column slice.
// Each block stages a 128x64 fW slice (32KB) -> ~5 resident blocks/SM.
extern __shared__ float s_w[];   // [D * 64]

__global__ __launch_bounds__(256) void k_pre(const float* __restrict__ x,
                                             const float* __restrict__ fW,
                                             const float* __restrict__ wW,
                                             const int* __restrict__ src,
                                             const int* __restrict__ tgt) {
    __shared__ float xs[D][NB + 2];   // k-major x tile, padded (8B-aligned rows)
    __shared__ float wWs[2 * D];
    __shared__ float red[128];
    int tid = threadIdx.x;
    int blk = blockIdx.x >> 2;
    int isQ = blockIdx.x & 1;
    int jh  = (blockIdx.x >> 1) & 1;
    int nb  = blk * NB;

    // direct scatter: 128 edges per block, hidden behind staging
    if (tid < 128) {
        int e = blockIdx.x * 128 + tid;
        int t = tgt[e];
        int pos = atomicAdd(&g_cursor[t], 1);
        if (pos < CAP) g_bucket[t * CAP + pos] = src[e];
    }

    // stage fW slice [128 rows x 64 cols] (32KB, 8 float4/thread), x tile, wW
    {
        const float* base = fW + (isQ ? D * D : 0) + jh * 64;
        float4*      d4   = reinterpret_cast<float4*>(s_w);
#pragma unroll
        for (int r = 0; r < 8; r++) {
            int idx = tid + r * 256;          // 0..2047 float4
            int row = idx >> 4, c4 = idx & 15;
            d4[idx] = *reinterpret_cast<const float4*>(base + row * D + c4 * 4);
        }
    }
    for (int i = tid; i < NB * D; i += 256) {
        int n = i >> 7, k = i & 127;
        xs[k][n] = x[(nb + n) * D + k];
    }
    wWs[tid] = wW[tid];
    __syncthreads();

    // each thread: column j (of 64), 4 nodes, 2 packed f32x2 accumulators
    int j = tid & 63, g = tid >> 6;
    int xbase = g * 4;
    const float* sw = s_w + j;
    unsigned long long a0 = 0, a1 = 0;

#pragma unroll 8
    for (int k = 0; k < D; k++) {
        float w = sw[k * 64];
        unsigned long long ww;
        asm("mov.b64 %0,{%1,%1};" : "=l"(ww) : "f"(w));
        const unsigned long long* xr =
            reinterpret_cast<const unsigned long long*>(&xs[k][xbase]);
        unsigned long long x0 = xr[0], x1 = xr[1];
        asm("fma.rn.f32x2 %0,%1,%2,%0;" : "+l"(a0) : "l"(x0), "l"(ww));
        asm("fma.rn.f32x2 %0,%1,%2,%0;" : "+l"(a1) : "l"(x1), "l"(ww));
    }

    float* dst = (isQ ? g_Q : g_P) + jh * 64;
    float lo, hi;
#define STORE_PAIR(acc, i) \
    asm("mov.b64 {%0,%1},%2;" : "=f"(lo), "=f"(hi) : "l"(acc)); \
    dst[(nb + xbase + 2*(i)    ) * D + j] = lo; \
    dst[(nb + xbase + 2*(i) + 1) * D + j] = hi;
    STORE_PAIR(a0, 0) STORE_PAIR(a1, 1)
#undef STORE_PAIR

    // s,t + exp: one writer per node tile (isQ==0 && jh==0 blocks)
    if (blockIdx.x == (blk << 2)) {
        if (tid < 128) {
            int n = tid & 15, half = (tid >> 4) & 1, q = tid >> 5;
            const float* wv = wWs + half * D;
            float p = 0.f;
#pragma unroll 8
            for (int k = q * 32; k < q * 32 + 32; k++) p = fmaf(xs[k][n], wv[k], p);
            red[tid] = p;
        }
        __syncthreads();
        if (tid < 32) {
            float v = red[tid] + red[tid + 32] + red[tid + 64] + red[tid + 96];
            float ev = __expf(v);
            int n = tid & 15, half = tid >> 4;
            if (half) g_et[nb + n] = ev; else g_es[nb + n] = ev;
        }
    }
}

// ---------------- kernel 2: block-per-node aggregation, 4 warps split edges ----------------
__global__ __launch_bounds__(128) void k_agg(float* __restrict__ out,
                                             const float* __restrict__ fb) {
    __shared__ float4 sacc[4][32];
    __shared__ float  sasum[4];
    int n = blockIdx.x, tid = threadIdx.x, lane = tid & 31, wid = tid >> 5;

    int cnt = min(g_cursor[n], CAP);
    const int* bk = &g_bucket[n * CAP];

    // contiguous per-warp chunk (short chains, batch-4 ILP gathers)
    int chunk = (cnt + 3) >> 2;
    int b0 = min(wid * chunk, cnt);
    int e0 = min(b0 + chunk, cnt);

    float4 q4 = *reinterpret_cast<const float4*>(&g_Q[n * D + lane * 4]);
    float4 f4 = *reinterpret_cast<const float4*>(&fb[lane * 4]);
    float4 qf = make_float4(q4.x + f4.x, q4.y + f4.y, q4.z + f4.z, q4.w + f4.w);

    float4 acc = make_float4(0.f, 0.f, 0.f, 0.f);
    float asum = 0.f;

    int i = b0;
    for (; i + 4 <= e0; i += 4) {
        int   sid[4];
        float w[4];
#pragma unroll
        for (int u = 0; u < 4; u++) sid[u] = __ldg(bk + i + u);   // independent, MLP 4
#pragma unroll
        for (int u = 0; u < 4; u++) w[u] = g_es[sid[u]];          // one dep hop, MLP 4
#pragma unroll
        for (int u = 0; u < 4; u++) {
            float4 p = *reinterpret_cast<const float4*>(&g_P[sid[u] * D + lane * 4]);
            acc.x = fmaf(fmaxf(p.x + qf.x, 0.f), w[u], acc.x);
            acc.y = fmaf(fmaxf(p.y + qf.y, 0.f), w[u], acc.y);
            acc.z = fmaf(fmaxf(p.z + qf.z, 0.f), w[u], acc.z);
            acc.w = fmaf(fmaxf(p.w + qf.w, 0.f), w[u], acc.w);
            asum += w[u];
        }
    }
    for (; i < e0; i++) {
        int   sid = __ldg(bk + i);
        float w   = g_es[sid];
        float4 p  = *reinterpret_cast<const float4*>(&g_P[sid * D + lane * 4]);
        acc.x = fmaf(fmaxf(p.x + qf.x, 0.f), w, acc.x);
        acc.y = fmaf(fmaxf(p.y + qf.y, 0.f), w, acc.y);
        acc.z = fmaf(fmaxf(p.z + qf.z, 0.f), w, acc.z);
        acc.w = fmaf(fmaxf(p.w + qf.w, 0.f), w, acc.w);
        asum += w;
    }

    sacc[wid][lane] = acc;
    if (lane == 0) sasum[wid] = asum;
    __syncthreads();
    if (tid == 0) g_cursor[n] = 0;   // reset for next replay (all reads done)

    const float* sp = reinterpret_cast<const float*>(sacc);
    float a = sp[tid] + sp[128 + tid] + sp[256 + tid] + sp[384 + tid];
    float s = sasum[0] + sasum[1] + sasum[2] + sasum[3];
    float et = g_et[n];
    out[n * D + tid] = (et * a) / (et * s + EPSF);   // exp(s+t)=es*et; EPS outside
}

// ---------------- launch: two graph nodes ----------------
extern "C" void kernel_launch(void* const* d_in, const int* in_sizes, int n_in,
                              void* d_out, int out_size) {
    const float* x   = (const float*)d_in[0];
    const int*   src = (const int*)  d_in[2];
    const int*   tgt = (const int*)  d_in[3];
    const float* fW  = (const float*)d_in[6];
    const float* fb  = (const float*)d_in[7];
    const float* wW  = (const float*)d_in[8];
    float*       out = (float*)d_out;

    k_pre<<<512, 256, D * 64 * sizeof(float)>>>(x, fW, wW, src, tgt);
    k_agg<<<NODES, 128>>>(out, fb);
}